// round 16
// baseline (speedup 1.0000x reference)
#include <cuda_runtime.h>
#include <cuda_fp16.h>

// Problem constants (fixed shapes per reference setup_inputs)
#define BB    4
#define HH    352            // rows; 352 = 32 * 11
#define WW    1216           // cols; 1216 = 4 * 304, 304 = 16 * 19
#define PLANE (HH * WW)      // 428032
#define NPIX  (BB * PLANE)   // 1712128
#define NGRP  (NPIX / 4)     // 428032  (4-px groups), PLANE/4 = 107008
#define GPR   304            // groups per row
#define HGRP  (NGRP / 2)     // 214016 groups per half-batch (2 images)

// Weight storage (center-tap identity: both dilations' (1,1) taps pre-summed)
//  - g_wmain: 8 non-center taps per group, uint4 jj =
//      { w1 px01, w2 px01, w1 px23, w2 px23 }, tap j = jj<4 ? jj : jj+1.
//    Tap-major swizzle in 32-group blocks: idx = (g>>5)*256 + jj*32 + (g&31)
//  - g_wctrp: merged center weights PAIRED by vertical row-pair:
//      pair p = b*(PLANE/8) + (gh>>1)*GPR + gg,
//      uint4 = { A.c01, A.c23, B.c01, B.c23 }  (A = even row, B = odd row)
__device__ uint4  g_wmain[(size_t)NGRP * 8];   // 54.8 MB
__device__ uint4  g_wctrp[(size_t)NGRP / 2];   // 3.4 MB
__device__ __half g_xa[NPIX];                  // 3.4 MB  (fp16 ping)
__device__ __half g_xb[NPIX];                  // 3.4 MB  (fp16 pong)

// ---- x row loads: only the 8 used columns (px w0-2 .. w0+5), zero-padded.
// xr[0..7] = window cols 2..9 of the old 12-wide window.
static __device__ __forceinline__ void load_row8(
    const float* __restrict__ xbm, int hh, int w0, int gg, float xr[8])
{
    bool rok = (hh >= 0) && (hh < HH);
    const float* rowp = xbm + hh * WW + w0;
    float2 a = make_float2(0.f, 0.f);
    float4 m = make_float4(0.f, 0.f, 0.f, 0.f);
    float2 b = make_float2(0.f, 0.f);
    if (rok) {
        if (gg > 0)       a = __ldcs((const float2*)(rowp - 2));
        m = __ldcs((const float4*)rowp);
        if (gg < GPR - 1) b = __ldcs((const float2*)(rowp + 4));
    }
    xr[0] = a.x; xr[1] = a.y;
    xr[2] = m.x; xr[3] = m.y; xr[4] = m.z; xr[5] = m.w;
    xr[6] = b.x; xr[7] = b.y;
}

static __device__ __forceinline__ void load_row8(
    const __half* __restrict__ xbm, int hh, int w0, int gg, float xr[8])
{
    bool rok = (hh >= 0) && (hh < HH);
    const __half* rowp = xbm + hh * WW + w0;
    unsigned int u23 = 0u, u45 = 0u, u67 = 0u, u89 = 0u;
    if (rok) {
        if (gg > 0)       u23 = *(const unsigned int*)(rowp - 2);
        uint2 mm = *(const uint2*)rowp;
        u45 = mm.x; u67 = mm.y;
        if (gg < GPR - 1) u89 = *(const unsigned int*)(rowp + 4);
    }
    float2 f;
    f = __half22float2(*(const __half2*)&u23); xr[0] = f.x; xr[1] = f.y;
    f = __half22float2(*(const __half2*)&u45); xr[2] = f.x; xr[3] = f.y;
    f = __half22float2(*(const __half2*)&u67); xr[4] = f.x; xr[5] = f.y;
    f = __half22float2(*(const __half2*)&u89); xr[6] = f.x; xr[7] = f.y;
}

// ---- group stores, fp32 and fp16 destination variants ----
static __device__ __forceinline__ void store_grp(float* op, const float a[4]) {
    *(float4*)op = make_float4(a[0], a[1], a[2], a[3]);
}
static __device__ __forceinline__ void store_grp(__half* op, const float a[4]) {
    __half2 lo = __floats2half2_rn(a[0], a[1]);
    __half2 hi = __floats2half2_rn(a[2], a[3]);
    uint2 u;
    u.x = *(const unsigned int*)&lo;
    u.y = *(const unsigned int*)&hi;
    *(uint2*)op = u;
}

// Dilation-1 contributions of one full kernel row (taps R0..R2, dr=0 or 2).
// xr[0..7] = px w0-2 .. w0+5; output px i has center xr[2+i].
static __device__ __forceinline__ void d1_row(
    const float xr[8], uint4 R0, uint4 R1, uint4 R2, float acc[4])
{
    const uint4 R[3] = {R0, R1, R2};
#pragma unroll
    for (int dc = 0; dc < 3; dc++) {
        float2 a01 = __half22float2(*(const __half2*)&R[dc].x);
        float2 a23 = __half22float2(*(const __half2*)&R[dc].z);
        acc[0] += a01.x * xr[1 + dc];
        acc[1] += a01.y * xr[2 + dc];
        acc[2] += a23.x * xr[3 + dc];
        acc[3] += a23.y * xr[4 + dc];
    }
}

// Dilation-2 contributions of one full kernel row (dr=0 or 2).
static __device__ __forceinline__ void d2_row(
    const float xr[8], uint4 R0, uint4 R1, uint4 R2, float acc[4])
{
    const uint4 R[3] = {R0, R1, R2};
#pragma unroll
    for (int dc = 0; dc < 3; dc++) {
        float2 b01 = __half22float2(*(const __half2*)&R[dc].y);
        float2 b23 = __half22float2(*(const __half2*)&R[dc].w);
        acc[0] += b01.x * xr[0 + 2 * dc];
        acc[1] += b01.y * xr[1 + 2 * dc];
        acc[2] += b23.x * xr[2 + 2 * dc];
        acc[3] += b23.y * xr[3 + 2 * dc];
    }
}

// Middle kernel row (dr=1): non-center taps (dc=0 L, dc=2 R), both
// dilations, plus merged center weights (c01, c23).
static __device__ __forceinline__ void mid_row(
    const float xr[8], uint4 L, uint4 R,
    unsigned int c01u, unsigned int c23u, float acc[4])
{
    float2 la = __half22float2(*(const __half2*)&L.x);
    float2 lA = __half22float2(*(const __half2*)&L.z);
    acc[0] += la.x * xr[1]; acc[1] += la.y * xr[2];
    acc[2] += lA.x * xr[3]; acc[3] += lA.y * xr[4];
    float2 ra = __half22float2(*(const __half2*)&R.x);
    float2 rA = __half22float2(*(const __half2*)&R.z);
    acc[0] += ra.x * xr[3]; acc[1] += ra.y * xr[4];
    acc[2] += rA.x * xr[5]; acc[3] += rA.y * xr[6];
    float2 lb = __half22float2(*(const __half2*)&L.y);
    float2 lB = __half22float2(*(const __half2*)&L.w);
    acc[0] += lb.x * xr[0]; acc[1] += lb.y * xr[1];
    acc[2] += lB.x * xr[2]; acc[3] += lB.y * xr[3];
    float2 rb = __half22float2(*(const __half2*)&R.y);
    float2 rB = __half22float2(*(const __half2*)&R.w);
    acc[0] += rb.x * xr[4]; acc[1] += rb.y * xr[5];
    acc[2] += rB.x * xr[6]; acc[3] += rB.y * xr[7];
    float2 c01 = __half22float2(*(const __half2*)&c01u);
    float2 c23 = __half22float2(*(const __half2*)&c23u);
    acc[0] += c01.x * xr[2]; acc[1] += c01.y * xr[3];
    acc[2] += c23.x * xr[4]; acc[3] += c23.y * xr[5];
}

// ---------------------------------------------------------------------------
// prep: softmax + fuse scaling for one HALF-BATCH (2 images).
// Thread local-u handles 2 px; absolute u = base_u + local.
// ---------------------------------------------------------------------------
__global__ __launch_bounds__(512) void prep_kernel(
    const float* __restrict__ g1,
    const float* __restrict__ g2,
    const float* __restrict__ fu,
    uint4* __restrict__ wmain,
    uint4* __restrict__ wctrp,
    int base_u)
{
    int u  = base_u + blockIdx.x * 512 + threadIdx.x;
    int g  = u >> 1;
    int tz = u & 1;
    int px = g * 4 + tz * 2;                   // flat pixel over (b,h,w)
    int b  = px / PLANE;
    int hw = px - b * PLANE;
    int base9 = b * 9 * PLANE + hw;
    int base2 = b * 2 * PLANE + hw;

    float a[9][2], c[9][2];
#pragma unroll
    for (int t = 0; t < 9; t++) {
        *(float2*)a[t] = __ldcs((const float2*)(g1 + base9 + t * PLANE));
        *(float2*)c[t] = __ldcs((const float2*)(g2 + base9 + t * PLANE));
    }
    float2 f1v = __ldcs((const float2*)(fu + base2));
    float2 f2v = __ldcs((const float2*)(fu + base2 + PLANE));
    float f1a[2] = {f1v.x, f1v.y};
    float f2a[2] = {f2v.x, f2v.y};

#pragma unroll
    for (int i = 0; i < 2; i++) {
        float s1 = 0.f, s2 = 0.f;
#pragma unroll
        for (int t = 0; t < 9; t++) {
            float e1 = __expf(a[t][i]); a[t][i] = e1; s1 += e1;
            float e2 = __expf(c[t][i]); c[t][i] = e2; s2 += e2;
        }
        float r1 = f1a[i] / s1;
        float r2 = f2a[i] / s2;
#pragma unroll
        for (int t = 0; t < 9; t++) { a[t][i] *= r1; c[t][i] *= r2; }
    }

#pragma unroll
    for (int jj = 0; jj < 8; jj++) {
        int j = (jj < 4) ? jj : jj + 1;
        __half2 hw1 = __floats2half2_rn(a[j][0], a[j][1]);
        __half2 hw2 = __floats2half2_rn(c[j][0], c[j][1]);
        uint2 uu;
        uu.x = *(const unsigned int*)&hw1;
        uu.y = *(const unsigned int*)&hw2;
        ((uint2*)&wmain[(size_t)(g >> 5) * 256 + jj * 32 + (g & 31)])[tz] = uu;
    }
    // merged center weight -> paired layout {A.c01, A.c23, B.c01, B.c23}
    __half2 hc = __floats2half2_rn(a[4][0] + c[4][0], a[4][1] + c[4][1]);
    int h  = hw / WW;
    int gg = (hw - h * WW) >> 2;
    int pi = b * (PLANE / 8) + (h >> 1) * GPR + gg;
    ((unsigned int*)&wctrp[pi])[(h & 1) * 2 + tz] = *(const unsigned int*)&hc;
}

// ---------------------------------------------------------------------------
// prop: one propagation iteration over a half-batch (gridDim.z = 2; all
// pointers pre-offset). Block (16,16): 64-px x 32-row tile, 2 rows/thread,
// streaming the 6 shared window rows; each weight record one LDG.
// ---------------------------------------------------------------------------
template <typename Tin, typename Tout>
__global__ __launch_bounds__(256, 3) void prop_kernel(
    const Tin* __restrict__ xin,
    const uint4* __restrict__ wmain,
    const uint4* __restrict__ wctrp,
    Tout* __restrict__ xout)
{
    int tx = threadIdx.x;              // 0..15 group-in-tile
    int ty = threadIdx.y;              // 0..15 row-pair-in-tile
    int bx = blockIdx.x, by = blockIdx.y, b = blockIdx.z;
    int gg = bx * 16 + tx;
    int gh = by * 32 + ty * 2;         // group A row (even); B = gh+1
    int w0 = gg * 4;
    const Tin* xbm = xin + b * PLANE;

    int gA = b * (PLANE / 4) + gh * GPR + gg;
    int gB = gA + GPR;
    const uint4* wA = wmain + (size_t)(gA >> 5) * 256 + (gA & 31);
    const uint4* wB = wmain + (size_t)(gB >> 5) * 256 + (gB & 31);
    int pi = b * (PLANE / 8) + (gh >> 1) * GPR + gg;

    float accA[4] = {0.f, 0.f, 0.f, 0.f};
    float accB[4] = {0.f, 0.f, 0.f, 0.f};
    uint4 A0, A1, A2, B0, B1, B2;
    float xr[8];

    // Stream window rows gh-2 .. gh+3. A's window rows = wr, B's = wr-1.
    load_row8(xbm, gh - 2, w0, gg, xr);
    A0 = __ldcg(wA + 0); A1 = __ldcg(wA + 32); A2 = __ldcg(wA + 64);
    d2_row(xr, A0, A1, A2, accA);

    load_row8(xbm, gh - 1, w0, gg, xr);
    d1_row(xr, A0, A1, A2, accA);
    B0 = __ldcg(wB + 0); B1 = __ldcg(wB + 32); B2 = __ldcg(wB + 64);
    d2_row(xr, B0, B1, B2, accB);

    load_row8(xbm, gh, w0, gg, xr);
    A0 = __ldcg(wA + 96); A1 = __ldcg(wA + 128);
    uint4 cc = __ldcg(&wctrp[pi]);     // {A.c01, A.c23, B.c01, B.c23}
    mid_row(xr, A0, A1, cc.x, cc.y, accA);
    d1_row(xr, B0, B1, B2, accB);

    load_row8(xbm, gh + 1, w0, gg, xr);
    A0 = __ldcg(wA + 160); A1 = __ldcg(wA + 192); A2 = __ldcg(wA + 224);
    d1_row(xr, A0, A1, A2, accA);
    B0 = __ldcg(wB + 96); B1 = __ldcg(wB + 128);
    mid_row(xr, B0, B1, cc.z, cc.w, accB);

    load_row8(xbm, gh + 2, w0, gg, xr);
    d2_row(xr, A0, A1, A2, accA);
    B0 = __ldcg(wB + 160); B1 = __ldcg(wB + 192); B2 = __ldcg(wB + 224);
    d1_row(xr, B0, B1, B2, accB);

    load_row8(xbm, gh + 3, w0, gg, xr);
    d2_row(xr, B0, B1, B2, accB);

    Tout* op = xout + b * PLANE + gh * WW + w0;
    store_grp(op, accA);
    store_grp(op + WW, accB);
}

// ---------------------------------------------------------------------------
// Launcher: two-phase pipeline. Default stream runs prep(h0), prep(h1);
// side stream k runs half-k's 8-iteration prop chain gated on its prep.
// ---------------------------------------------------------------------------
extern "C" void kernel_launch(void* const* d_in, const int* in_sizes, int n_in,
                              void* d_out, int out_size)
{
    const float* g1 = (const float*)d_in[0];
    const float* g2 = (const float*)d_in[1];
    const float* fu = (const float*)d_in[2];
    const float* x0 = (const float*)d_in[3];
    float* out = (float*)d_out;

    uint4 *wmain, *wctrp;
    __half *xa, *xb;
    cudaGetSymbolAddress((void**)&wmain, g_wmain);
    cudaGetSymbolAddress((void**)&wctrp, g_wctrp);
    cudaGetSymbolAddress((void**)&xa, g_xa);
    cudaGetSymbolAddress((void**)&xb, g_xb);

    static cudaStream_t s[2];
    static cudaEvent_t evP[2], evD[2];
    static bool init = false;
    if (!init) {
        for (int k = 0; k < 2; k++) {
            cudaStreamCreateWithFlags(&s[k], cudaStreamNonBlocking);
            cudaEventCreateWithFlags(&evP[k], cudaEventDisableTiming);
            cudaEventCreateWithFlags(&evD[k], cudaEventDisableTiming);
        }
        init = true;
    }

    dim3 pblk(16, 16, 1);
    dim3 pgrd(GPR / 16, HH / 32, 2);      // (19, 11, 2) per half

    for (int k = 0; k < 2; k++) {
        prep_kernel<<<836, 512>>>(g1, g2, fu, wmain, wctrp, k * 2 * HGRP);
        cudaEventRecord(evP[k], 0);

        cudaStreamWaitEvent(s[k], evP[k], 0);
        size_t po = (size_t)k * 2 * PLANE;   // pixel offset of half k
        size_t go = (size_t)k * HGRP;        // group offset of half k
        const float*  x0h = x0 + po;
        float*        outh = out + po;
        __half* xah = xa + po;
        __half* xbh = xb + po;
        const uint4* wmh = wmain + go * 8;
        const uint4* wch = wctrp + go / 2;

        prop_kernel<float,  __half><<<pgrd, pblk, 0, s[k]>>>(x0h, wmh, wch, xah);
        prop_kernel<__half, __half><<<pgrd, pblk, 0, s[k]>>>(xah, wmh, wch, xbh);
        prop_kernel<__half, __half><<<pgrd, pblk, 0, s[k]>>>(xbh, wmh, wch, xah);
        prop_kernel<__half, __half><<<pgrd, pblk, 0, s[k]>>>(xah, wmh, wch, xbh);
        prop_kernel<__half, __half><<<pgrd, pblk, 0, s[k]>>>(xbh, wmh, wch, xah);
        prop_kernel<__half, __half><<<pgrd, pblk, 0, s[k]>>>(xah, wmh, wch, xbh);
        prop_kernel<__half, __half><<<pgrd, pblk, 0, s[k]>>>(xbh, wmh, wch, xah);
        prop_kernel<__half, float ><<<pgrd, pblk, 0, s[k]>>>(xah, wmh, wch, outh);
        cudaEventRecord(evD[k], s[k]);
    }

    cudaStreamWaitEvent(0, evD[0], 0);
    cudaStreamWaitEvent(0, evD[1], 0);
}

// round 17
// speedup vs baseline: 1.0284x; 1.0284x over previous
#include <cuda_runtime.h>
#include <cuda_fp16.h>

// Problem constants (fixed shapes per reference setup_inputs)
#define BB    4
#define HH    352            // rows; 352 = 32 * 11
#define WW    1216           // cols; 1216 = 4 * 304, 304 = 16 * 19
#define PLANE (HH * WW)      // 428032
#define NPIX  (BB * PLANE)   // 1712128
#define NGRP  (NPIX / 4)     // 428032  (4-px groups), PLANE/4 = 107008
#define GPR   304            // groups per row
#define HGRP  (NGRP / 2)     // 214016 groups per half-batch (2 images)

// Weight storage (center-tap identity: both dilations' (1,1) taps pre-summed)
//  - g_wmain: 8 non-center taps per group, uint4 jj =
//      { w1 px01, w2 px01, w1 px23, w2 px23 }, tap j = jj<4 ? jj : jj+1.
//    Tap-major swizzle in 32-group blocks: idx = (g>>5)*256 + jj*32 + (g&31)
//  - g_wctrp: merged center weights PAIRED by vertical row-pair:
//      pair p = b*(PLANE/8) + (gh>>1)*GPR + gg,
//      uint4 = { A.c01, A.c23, B.c01, B.c23 }  (A = even row, B = odd row)
__device__ uint4  g_wmain[(size_t)NGRP * 8];   // 54.8 MB
__device__ uint4  g_wctrp[(size_t)NGRP / 2];   // 3.4 MB
__device__ __half g_xa[NPIX];                  // 3.4 MB  (fp16 ping)
__device__ __half g_xb[NPIX];                  // 3.4 MB  (fp16 pong)

// ---- x row loads (zero-padded, 12-wide window, uniform wide loads) ----
static __device__ __forceinline__ void load_row(
    const float* __restrict__ xbm, int hh, int w0, float xr[12])
{
    bool rok = (hh >= 0) && (hh < HH);
    const float* rowp = xbm + hh * WW;
#pragma unroll
    for (int q = 0; q < 3; q++) {
        int c0 = w0 + (q - 1) * 4;
        float4 v = make_float4(0.f, 0.f, 0.f, 0.f);
        if (rok && c0 >= 0 && c0 < WW)
            v = __ldcs((const float4*)(rowp + c0));   // read-once fp32 x0
        xr[q * 4 + 0] = v.x;
        xr[q * 4 + 1] = v.y;
        xr[q * 4 + 2] = v.z;
        xr[q * 4 + 3] = v.w;
    }
}

static __device__ __forceinline__ void load_row(
    const __half* __restrict__ xbm, int hh, int w0, float xr[12])
{
    bool rok = (hh >= 0) && (hh < HH);
    const __half* rowp = xbm + hh * WW;
#pragma unroll
    for (int q = 0; q < 3; q++) {
        int c0 = w0 + (q - 1) * 4;
        uint2 u = make_uint2(0u, 0u);        // 0x0000 == half(0.0)
        if (rok && c0 >= 0 && c0 < WW)
            u = *(const uint2*)(rowp + c0);
        float2 lo = __half22float2(*(const __half2*)&u.x);
        float2 hi = __half22float2(*(const __half2*)&u.y);
        xr[q * 4 + 0] = lo.x;
        xr[q * 4 + 1] = lo.y;
        xr[q * 4 + 2] = hi.x;
        xr[q * 4 + 3] = hi.y;
    }
}

// ---- group stores, fp32 and fp16 destination variants ----
static __device__ __forceinline__ void store_grp(float* op, const float a[4]) {
    *(float4*)op = make_float4(a[0], a[1], a[2], a[3]);
}
static __device__ __forceinline__ void store_grp(__half* op, const float a[4]) {
    __half2 lo = __floats2half2_rn(a[0], a[1]);
    __half2 hi = __floats2half2_rn(a[2], a[3]);
    uint2 u;
    u.x = *(const unsigned int*)&lo;
    u.y = *(const unsigned int*)&hi;
    *(uint2*)op = u;
}

// Dilation-1 contributions of one full kernel row (taps R0..R2, dr=0 or 2).
// Window cols 0..11 = px w0-4 .. w0+7; output px i has center col 4+i.
static __device__ __forceinline__ void d1_row(
    const float xr[12], uint4 R0, uint4 R1, uint4 R2, float acc[4])
{
    const uint4 R[3] = {R0, R1, R2};
#pragma unroll
    for (int dc = 0; dc < 3; dc++) {
        float2 a01 = __half22float2(*(const __half2*)&R[dc].x);
        float2 a23 = __half22float2(*(const __half2*)&R[dc].z);
        acc[0] += a01.x * xr[3 + dc];
        acc[1] += a01.y * xr[4 + dc];
        acc[2] += a23.x * xr[5 + dc];
        acc[3] += a23.y * xr[6 + dc];
    }
}

// Dilation-2 contributions of one full kernel row (dr=0 or 2).
static __device__ __forceinline__ void d2_row(
    const float xr[12], uint4 R0, uint4 R1, uint4 R2, float acc[4])
{
    const uint4 R[3] = {R0, R1, R2};
#pragma unroll
    for (int dc = 0; dc < 3; dc++) {
        float2 b01 = __half22float2(*(const __half2*)&R[dc].y);
        float2 b23 = __half22float2(*(const __half2*)&R[dc].w);
        acc[0] += b01.x * xr[2 + 2 * dc];
        acc[1] += b01.y * xr[3 + 2 * dc];
        acc[2] += b23.x * xr[4 + 2 * dc];
        acc[3] += b23.y * xr[5 + 2 * dc];
    }
}

// Middle kernel row (dr=1): non-center taps (dc=0 L, dc=2 R), both
// dilations, plus merged center weights (c01, c23).
static __device__ __forceinline__ void mid_row(
    const float xr[12], uint4 L, uint4 R,
    unsigned int c01u, unsigned int c23u, float acc[4])
{
    float2 la = __half22float2(*(const __half2*)&L.x);
    float2 lA = __half22float2(*(const __half2*)&L.z);
    acc[0] += la.x * xr[3]; acc[1] += la.y * xr[4];
    acc[2] += lA.x * xr[5]; acc[3] += lA.y * xr[6];
    float2 ra = __half22float2(*(const __half2*)&R.x);
    float2 rA = __half22float2(*(const __half2*)&R.z);
    acc[0] += ra.x * xr[5]; acc[1] += ra.y * xr[6];
    acc[2] += rA.x * xr[7]; acc[3] += rA.y * xr[8];
    float2 lb = __half22float2(*(const __half2*)&L.y);
    float2 lB = __half22float2(*(const __half2*)&L.w);
    acc[0] += lb.x * xr[2]; acc[1] += lb.y * xr[3];
    acc[2] += lB.x * xr[4]; acc[3] += lB.y * xr[5];
    float2 rb = __half22float2(*(const __half2*)&R.y);
    float2 rB = __half22float2(*(const __half2*)&R.w);
    acc[0] += rb.x * xr[6]; acc[1] += rb.y * xr[7];
    acc[2] += rB.x * xr[8]; acc[3] += rB.y * xr[9];
    float2 c01 = __half22float2(*(const __half2*)&c01u);
    float2 c23 = __half22float2(*(const __half2*)&c23u);
    acc[0] += c01.x * xr[4]; acc[1] += c01.y * xr[5];
    acc[2] += c23.x * xr[6]; acc[3] += c23.y * xr[7];
}

// ---------------------------------------------------------------------------
// prep: softmax + fuse scaling for one HALF-BATCH (2 images).
// Thread local-u handles 2 px; absolute u = base_u + local.
// ---------------------------------------------------------------------------
__global__ __launch_bounds__(512) void prep_kernel(
    const float* __restrict__ g1,
    const float* __restrict__ g2,
    const float* __restrict__ fu,
    uint4* __restrict__ wmain,
    uint4* __restrict__ wctrp,
    int base_u)
{
    int u  = base_u + blockIdx.x * 512 + threadIdx.x;
    int g  = u >> 1;
    int tz = u & 1;
    int px = g * 4 + tz * 2;                   // flat pixel over (b,h,w)
    int b  = px / PLANE;
    int hw = px - b * PLANE;
    int base9 = b * 9 * PLANE + hw;
    int base2 = b * 2 * PLANE + hw;

    float a[9][2], c[9][2];
#pragma unroll
    for (int t = 0; t < 9; t++) {
        *(float2*)a[t] = __ldcs((const float2*)(g1 + base9 + t * PLANE));
        *(float2*)c[t] = __ldcs((const float2*)(g2 + base9 + t * PLANE));
    }
    float2 f1v = __ldcs((const float2*)(fu + base2));
    float2 f2v = __ldcs((const float2*)(fu + base2 + PLANE));
    float f1a[2] = {f1v.x, f1v.y};
    float f2a[2] = {f2v.x, f2v.y};

#pragma unroll
    for (int i = 0; i < 2; i++) {
        float s1 = 0.f, s2 = 0.f;
#pragma unroll
        for (int t = 0; t < 9; t++) {
            float e1 = __expf(a[t][i]); a[t][i] = e1; s1 += e1;
            float e2 = __expf(c[t][i]); c[t][i] = e2; s2 += e2;
        }
        float r1 = f1a[i] / s1;
        float r2 = f2a[i] / s2;
#pragma unroll
        for (int t = 0; t < 9; t++) { a[t][i] *= r1; c[t][i] *= r2; }
    }

#pragma unroll
    for (int jj = 0; jj < 8; jj++) {
        int j = (jj < 4) ? jj : jj + 1;
        __half2 hw1 = __floats2half2_rn(a[j][0], a[j][1]);
        __half2 hw2 = __floats2half2_rn(c[j][0], c[j][1]);
        uint2 uu;
        uu.x = *(const unsigned int*)&hw1;
        uu.y = *(const unsigned int*)&hw2;
        ((uint2*)&wmain[(size_t)(g >> 5) * 256 + jj * 32 + (g & 31)])[tz] = uu;
    }
    // merged center weight -> paired layout {A.c01, A.c23, B.c01, B.c23}
    __half2 hc = __floats2half2_rn(a[4][0] + c[4][0], a[4][1] + c[4][1]);
    int h  = hw / WW;
    int gg = (hw - h * WW) >> 2;
    int pi = b * (PLANE / 8) + (h >> 1) * GPR + gg;
    ((unsigned int*)&wctrp[pi])[(h & 1) * 2 + tz] = *(const unsigned int*)&hc;
}

// ---------------------------------------------------------------------------
// prop: one propagation iteration over a half-batch (gridDim.z = 2; all
// pointers pre-offset). Block (16,16): 64-px x 32-row tile, 2 rows/thread,
// streaming the 6 shared window rows; each weight record one LDG (8 main
// uint4 per group + 1 shared paired-center uint4 per row-pair).
// ---------------------------------------------------------------------------
template <typename Tin, typename Tout>
__global__ __launch_bounds__(256, 3) void prop_kernel(
    const Tin* __restrict__ xin,
    const uint4* __restrict__ wmain,
    const uint4* __restrict__ wctrp,
    Tout* __restrict__ xout)
{
    int tx = threadIdx.x;              // 0..15 group-in-tile
    int ty = threadIdx.y;              // 0..15 row-pair-in-tile
    int bx = blockIdx.x, by = blockIdx.y, b = blockIdx.z;
    int gg = bx * 16 + tx;
    int gh = by * 32 + ty * 2;         // group A row (even); B = gh+1
    int w0 = gg * 4;
    const Tin* xbm = xin + b * PLANE;

    int gA = b * (PLANE / 4) + gh * GPR + gg;
    int gB = gA + GPR;
    const uint4* wA = wmain + (size_t)(gA >> 5) * 256 + (gA & 31);
    const uint4* wB = wmain + (size_t)(gB >> 5) * 256 + (gB & 31);
    int pi = b * (PLANE / 8) + (gh >> 1) * GPR + gg;

    float accA[4] = {0.f, 0.f, 0.f, 0.f};
    float accB[4] = {0.f, 0.f, 0.f, 0.f};
    uint4 A0, A1, A2, B0, B1, B2;
    float xr[12];

    // Stream window rows gh-2 .. gh+3. A's window rows = wr, B's = wr-1.
    load_row(xbm, gh - 2, w0, xr);
    A0 = __ldcg(wA + 0); A1 = __ldcg(wA + 32); A2 = __ldcg(wA + 64);
    d2_row(xr, A0, A1, A2, accA);

    load_row(xbm, gh - 1, w0, xr);
    d1_row(xr, A0, A1, A2, accA);
    B0 = __ldcg(wB + 0); B1 = __ldcg(wB + 32); B2 = __ldcg(wB + 64);
    d2_row(xr, B0, B1, B2, accB);

    load_row(xbm, gh, w0, xr);
    A0 = __ldcg(wA + 96); A1 = __ldcg(wA + 128);
    uint4 cc = __ldcg(&wctrp[pi]);     // {A.c01, A.c23, B.c01, B.c23}
    mid_row(xr, A0, A1, cc.x, cc.y, accA);
    d1_row(xr, B0, B1, B2, accB);

    load_row(xbm, gh + 1, w0, xr);
    A0 = __ldcg(wA + 160); A1 = __ldcg(wA + 192); A2 = __ldcg(wA + 224);
    d1_row(xr, A0, A1, A2, accA);
    B0 = __ldcg(wB + 96); B1 = __ldcg(wB + 128);
    mid_row(xr, B0, B1, cc.z, cc.w, accB);

    load_row(xbm, gh + 2, w0, xr);
    d2_row(xr, A0, A1, A2, accA);
    B0 = __ldcg(wB + 160); B1 = __ldcg(wB + 192); B2 = __ldcg(wB + 224);
    d1_row(xr, B0, B1, B2, accB);

    load_row(xbm, gh + 3, w0, xr);
    d2_row(xr, B0, B1, B2, accB);

    Tout* op = xout + b * PLANE + gh * WW + w0;
    store_grp(op, accA);
    store_grp(op + WW, accB);
}

// ---------------------------------------------------------------------------
// Launcher: two-phase pipeline. Default stream runs prep(h0), prep(h1);
// side stream k runs half-k's 8-iteration prop chain gated on its prep.
// ---------------------------------------------------------------------------
extern "C" void kernel_launch(void* const* d_in, const int* in_sizes, int n_in,
                              void* d_out, int out_size)
{
    const float* g1 = (const float*)d_in[0];
    const float* g2 = (const float*)d_in[1];
    const float* fu = (const float*)d_in[2];
    const float* x0 = (const float*)d_in[3];
    float* out = (float*)d_out;

    uint4 *wmain, *wctrp;
    __half *xa, *xb;
    cudaGetSymbolAddress((void**)&wmain, g_wmain);
    cudaGetSymbolAddress((void**)&wctrp, g_wctrp);
    cudaGetSymbolAddress((void**)&xa, g_xa);
    cudaGetSymbolAddress((void**)&xb, g_xb);

    static cudaStream_t s[2];
    static cudaEvent_t evP[2], evD[2];
    static bool init = false;
    if (!init) {
        for (int k = 0; k < 2; k++) {
            cudaStreamCreateWithFlags(&s[k], cudaStreamNonBlocking);
            cudaEventCreateWithFlags(&evP[k], cudaEventDisableTiming);
            cudaEventCreateWithFlags(&evD[k], cudaEventDisableTiming);
        }
        init = true;
    }

    dim3 pblk(16, 16, 1);
    dim3 pgrd(GPR / 16, HH / 32, 2);      // (19, 11, 2) per half

    for (int k = 0; k < 2; k++) {
        prep_kernel<<<836, 512>>>(g1, g2, fu, wmain, wctrp, k * 2 * HGRP);
        cudaEventRecord(evP[k], 0);

        cudaStreamWaitEvent(s[k], evP[k], 0);
        size_t po = (size_t)k * 2 * PLANE;   // pixel offset of half k
        size_t go = (size_t)k * HGRP;        // group offset of half k
        const float*  x0h = x0 + po;
        float*        outh = out + po;
        __half* xah = xa + po;
        __half* xbh = xb + po;
        const uint4* wmh = wmain + go * 8;
        const uint4* wch = wctrp + go / 2;

        prop_kernel<float,  __half><<<pgrd, pblk, 0, s[k]>>>(x0h, wmh, wch, xah);
        prop_kernel<__half, __half><<<pgrd, pblk, 0, s[k]>>>(xah, wmh, wch, xbh);
        prop_kernel<__half, __half><<<pgrd, pblk, 0, s[k]>>>(xbh, wmh, wch, xah);
        prop_kernel<__half, __half><<<pgrd, pblk, 0, s[k]>>>(xah, wmh, wch, xbh);
        prop_kernel<__half, __half><<<pgrd, pblk, 0, s[k]>>>(xbh, wmh, wch, xah);
        prop_kernel<__half, __half><<<pgrd, pblk, 0, s[k]>>>(xah, wmh, wch, xbh);
        prop_kernel<__half, __half><<<pgrd, pblk, 0, s[k]>>>(xbh, wmh, wch, xah);
        prop_kernel<__half, float ><<<pgrd, pblk, 0, s[k]>>>(xah, wmh, wch, outh);
        cudaEventRecord(evD[k], s[k]);
    }

    cudaStreamWaitEvent(0, evD[0], 0);
    cudaStreamWaitEvent(0, evD[1], 0);
}